// round 2
// baseline (speedup 1.0000x reference)
#include <cuda_runtime.h>
#include <math_constants.h>

// Problem constants (fixed by the reference: B=8, Te=Td=2048, D=256)
#define B_  8
#define T_  2048
#define D_  256
#define BQ  64
#define BK  64
#define NTHREADS 256

#define KS_STRIDE 260   // D + 4 floats padding (conflict-free transpose reads)
#define PS_STRIDE 68    // BK + 4

// smem layout (floats):
//   Qt2 [D_/2][BQ] float2 = 16384 floats   (Qt2[d2][q] = (Q[q][2d2], Q[q][2d2+1]))
//   Kt2 [D_/2][BK] float2 = 16384 floats
//   Ks  [BK][KS_STRIDE]   = 16640 floats   (K natural, for GEMM2)
//   Ps  [BQ][PS_STRIDE]   =  4352 floats
// total = 53760 floats = 215040 bytes
#define SMEM_FLOATS ((D_/2)*BQ*2 + (D_/2)*BK*2 + BK*KS_STRIDE + BQ*PS_STRIDE)

// ---------- packed f32x2 helpers (SASS FFMA2 path; PTX-only per sm_103a) ----
__device__ __forceinline__ unsigned long long ffma2(unsigned long long a,
                                                    unsigned long long b,
                                                    unsigned long long c) {
    unsigned long long d;
    asm("fma.rn.f32x2 %0, %1, %2, %3;" : "=l"(d) : "l"(a), "l"(b), "l"(c));
    return d;
}
__device__ __forceinline__ unsigned long long mul2(unsigned long long a,
                                                   unsigned long long b) {
    unsigned long long d;
    asm("mul.rn.f32x2 %0, %1, %2;" : "=l"(d) : "l"(a), "l"(b));
    return d;
}
__device__ __forceinline__ unsigned long long pack2(float lo, float hi) {
    unsigned long long d;
    asm("mov.b64 %0, {%1, %2};" : "=l"(d) : "f"(lo), "f"(hi));
    return d;
}
__device__ __forceinline__ float2 unpack2(unsigned long long v) {
    float lo, hi;
    asm("mov.b64 {%0, %1}, %2;" : "=f"(lo), "=f"(hi) : "l"(v));
    return make_float2(lo, hi);
}

__global__ __launch_bounds__(NTHREADS, 1)
void luong_attn_kernel(const float* __restrict__ enc,
                       const float* __restrict__ dec,
                       float* __restrict__ out)
{
    extern __shared__ float sm[];
    float2* Qt2 = reinterpret_cast<float2*>(sm);            // [D_/2][BQ] f2
    float2* Kt2 = Qt2 + (D_/2) * BQ;                        // [D_/2][BK] f2
    float*  Ks  = reinterpret_cast<float*>(Kt2 + (D_/2) * BK); // [BK][KS_STRIDE]
    float*  Ps  = Ks + BK * KS_STRIDE;                      // [BQ][PS_STRIDE]

    const int b   = blockIdx.y;
    const int t0  = blockIdx.x * BQ;
    const int tid = threadIdx.x;
    const int ty  = tid >> 4;   // 0..15 -> owns q rows 4ty..4ty+3
    const int tx  = tid & 15;   // 0..15 -> e cols 4tx.. (GEMM1), d cols {4tx+64j} (GEMM2)

    const float* encb = enc + (size_t)b * T_ * D_;
    const float* decb = dec + (size_t)b * T_ * D_;

    // ---------------- Load Q tile -> Qt2 (transposed, d-paired), staged via Ks
    for (int idx = tid; idx < BQ * (D_ / 4); idx += NTHREADS) {
        int r  = idx / (D_ / 4);
        int c4 = idx % (D_ / 4);
        float4 v = reinterpret_cast<const float4*>(decb + (size_t)(t0 + r) * D_)[c4];
        *reinterpret_cast<float4*>(&Ks[r * KS_STRIDE + c4 * 4]) = v;
    }
    __syncthreads();
    {
        int rr = tid & 63;
        for (int c4 = tid >> 6; c4 < D_ / 4; c4 += 4) {
            float4 v = *reinterpret_cast<const float4*>(&Ks[rr * KS_STRIDE + c4 * 4]);
            Qt2[(2 * c4 + 0) * BQ + rr] = make_float2(v.x, v.y);
            Qt2[(2 * c4 + 1) * BQ + rr] = make_float2(v.z, v.w);
        }
    }
    __syncthreads();

    // ---------------- Flash accumulators (packed along d) ------------------
    float m[4], l[4];
    unsigned long long acc2[4][8];   // acc2[i][2j+h] = (ctx[d], ctx[d+1]), d = 4tx+64j+2h
    #pragma unroll
    for (int i = 0; i < 4; i++) {
        m[i] = -CUDART_INF_F;
        l[i] = 0.0f;
        #pragma unroll
        for (int j = 0; j < 8; j++) acc2[i][j] = 0ull;
    }

    // ---------------- Main loop over encoder (key) blocks ------------------
    for (int e0 = 0; e0 < T_; e0 += BK) {
        // Load K tile: gmem (coalesced) -> Ks natural
        for (int idx = tid; idx < BK * (D_ / 4); idx += NTHREADS) {
            int r  = idx / (D_ / 4);
            int c4 = idx % (D_ / 4);
            float4 v = reinterpret_cast<const float4*>(encb + (size_t)(e0 + r) * D_)[c4];
            *reinterpret_cast<float4*>(&Ks[r * KS_STRIDE + c4 * 4]) = v;
        }
        __syncthreads();
        // Transpose Ks -> Kt2 (d-paired)
        {
            int rr = tid & 63;
            for (int c4 = tid >> 6; c4 < D_ / 4; c4 += 4) {
                float4 v = *reinterpret_cast<const float4*>(&Ks[rr * KS_STRIDE + c4 * 4]);
                Kt2[(2 * c4 + 0) * BK + rr] = make_float2(v.x, v.y);
                Kt2[(2 * c4 + 1) * BK + rr] = make_float2(v.z, v.w);
            }
        }
        __syncthreads();

        // ---- GEMM1: S2[4q][4e] += (q_d*k_d, q_{d+1}*k_{d+1}) over d2 ------
        unsigned long long S2[4][4];
        #pragma unroll
        for (int i = 0; i < 4; i++)
            #pragma unroll
            for (int j = 0; j < 4; j++) S2[i][j] = 0ull;

        #pragma unroll 4
        for (int d2 = 0; d2 < D_ / 2; d2++) {
            ulonglong2 qa = *reinterpret_cast<const ulonglong2*>(Qt2 + d2 * BQ + (ty << 2));
            ulonglong2 qb = *reinterpret_cast<const ulonglong2*>(Qt2 + d2 * BQ + (ty << 2) + 2);
            ulonglong2 ka = *reinterpret_cast<const ulonglong2*>(Kt2 + d2 * BK + (tx << 2));
            ulonglong2 kb = *reinterpret_cast<const ulonglong2*>(Kt2 + d2 * BK + (tx << 2) + 2);
            unsigned long long q2[4] = {qa.x, qa.y, qb.x, qb.y};
            unsigned long long k2[4] = {ka.x, ka.y, kb.x, kb.y};
            #pragma unroll
            for (int i = 0; i < 4; i++)
                #pragma unroll
                for (int j = 0; j < 4; j++)
                    S2[i][j] = ffma2(q2[i], k2[j], S2[i][j]);
        }

        // ---- Online softmax over this key block ---------------------------
        #pragma unroll
        for (int i = 0; i < 4; i++) {
            float S[4];
            #pragma unroll
            for (int j = 0; j < 4; j++) {
                float2 s = unpack2(S2[i][j]);
                S[j] = s.x + s.y;
            }
            float bm = fmaxf(fmaxf(S[0], S[1]), fmaxf(S[2], S[3]));
            #pragma unroll
            for (int off = 1; off < 16; off <<= 1)
                bm = fmaxf(bm, __shfl_xor_sync(0xffffffffu, bm, off));
            float newm  = fmaxf(m[i], bm);
            float alpha = __expf(m[i] - newm);   // 0 when m[i] == -inf

            float p0 = __expf(S[0] - newm);
            float p1 = __expf(S[1] - newm);
            float p2 = __expf(S[2] - newm);
            float p3 = __expf(S[3] - newm);
            float rs = (p0 + p1) + (p2 + p3);
            #pragma unroll
            for (int off = 1; off < 16; off <<= 1)
                rs += __shfl_xor_sync(0xffffffffu, rs, off);

            l[i] = l[i] * alpha + rs;
            m[i] = newm;
            unsigned long long aa = pack2(alpha, alpha);
            #pragma unroll
            for (int j = 0; j < 8; j++) acc2[i][j] = mul2(acc2[i][j], aa);

            float4 pv = make_float4(p0, p1, p2, p3);
            *reinterpret_cast<float4*>(&Ps[((ty << 2) + i) * PS_STRIDE + (tx << 2)]) = pv;
        }
        __syncthreads();

        // ---- GEMM2: acc2[4q][8 d-pairs] += P[q][e] * K[e][d-pair] ---------
        const float* Pr0 = &Ps[((ty << 2) + 0) * PS_STRIDE];
        const float* Pr1 = &Ps[((ty << 2) + 1) * PS_STRIDE];
        const float* Pr2 = &Ps[((ty << 2) + 2) * PS_STRIDE];
        const float* Pr3 = &Ps[((ty << 2) + 3) * PS_STRIDE];
        #pragma unroll 2
        for (int e = 0; e < BK; e++) {
            unsigned long long pp0 = pack2(Pr0[e], Pr0[e]);
            unsigned long long pp1 = pack2(Pr1[e], Pr1[e]);
            unsigned long long pp2 = pack2(Pr2[e], Pr2[e]);
            unsigned long long pp3 = pack2(Pr3[e], Pr3[e]);
            #pragma unroll
            for (int j = 0; j < 4; j++) {
                ulonglong2 kk = *reinterpret_cast<const ulonglong2*>(
                    &Ks[e * KS_STRIDE + (tx << 2) + (j << 6)]);
                acc2[0][2*j+0] = ffma2(pp0, kk.x, acc2[0][2*j+0]);
                acc2[0][2*j+1] = ffma2(pp0, kk.y, acc2[0][2*j+1]);
                acc2[1][2*j+0] = ffma2(pp1, kk.x, acc2[1][2*j+0]);
                acc2[1][2*j+1] = ffma2(pp1, kk.y, acc2[1][2*j+1]);
                acc2[2][2*j+0] = ffma2(pp2, kk.x, acc2[2][2*j+0]);
                acc2[2][2*j+1] = ffma2(pp2, kk.y, acc2[2][2*j+1]);
                acc2[3][2*j+0] = ffma2(pp3, kk.x, acc2[3][2*j+0]);
                acc2[3][2*j+1] = ffma2(pp3, kk.y, acc2[3][2*j+1]);
            }
        }
        __syncthreads();   // before next iteration overwrites Ks/Kt2
    }

    // ---------------- Epilogue: out = [dec | acc / l] ----------------------
    #pragma unroll
    for (int i = 0; i < 4; i++) {
        float inv = 1.0f / l[i];
        size_t row = ((size_t)b * T_ + t0 + (ty << 2) + i) * (2 * D_);
        #pragma unroll
        for (int j = 0; j < 4; j++) {
            float2 a0 = unpack2(acc2[i][2*j+0]);
            float2 a1 = unpack2(acc2[i][2*j+1]);
            float4 v = make_float4(a0.x * inv, a0.y * inv, a1.x * inv, a1.y * inv);
            *reinterpret_cast<float4*>(&out[row + D_ + (tx << 2) + (j << 6)]) = v;
        }
    }
    // copy decoder rows into out[..., 0:256]
    for (int idx = tid; idx < BQ * (D_ / 4); idx += NTHREADS) {
        int r  = idx / (D_ / 4);
        int c4 = idx % (D_ / 4);
        float4 v = reinterpret_cast<const float4*>(decb + (size_t)(t0 + r) * D_)[c4];
        *reinterpret_cast<float4*>(&out[((size_t)b * T_ + t0 + r) * (2 * D_) + c4 * 4]) = v;
    }
}

extern "C" void kernel_launch(void* const* d_in, const int* in_sizes, int n_in,
                              void* d_out, int out_size)
{
    const float* enc = (const float*)d_in[0];  // encoder_outputs [8,2048,256]
    const float* dec = (const float*)d_in[1];  // decoder_outputs [8,2048,256]
    float* out = (float*)d_out;                // [8,2048,512]

    (void)in_sizes; (void)n_in; (void)out_size;

    static_assert(SMEM_FLOATS * sizeof(float) <= 232448, "smem over limit");
    cudaFuncSetAttribute(luong_attn_kernel,
                         cudaFuncAttributeMaxDynamicSharedMemorySize,
                         SMEM_FLOATS * (int)sizeof(float));

    dim3 grid(T_ / BQ, B_);
    luong_attn_kernel<<<grid, NTHREADS, SMEM_FLOATS * sizeof(float)>>>(enc, dec, out);
}

// round 3
// speedup vs baseline: 1.1690x; 1.1690x over previous
#include <cuda_runtime.h>
#include <math_constants.h>

// Problem constants (fixed by the reference: B=8, Te=Td=2048, D=256)
#define B_  8
#define T_  2048
#define D_  256
#define BQ  64
#define BK  64
#define NTHREADS 256

#define KS_STRIDE 260   // D + 4 floats padding
#define PS2_STRIDE 66   // BK + 2 (in float2 units)

// smem layout (floats):
//   Qt2 [D_/2][64] float2 (e-permuted) = 16384 floats
//   Kt2 [D_/2][64] float2 (e-permuted) = 16384 floats
//   Ks  [BK][KS_STRIDE]                = 16640 floats
//   Ps2 [BQ][PS2_STRIDE] float2        =  8448 floats
// total = 57856 floats = 231424 bytes (<= 232448 limit)
#define SMEM_FLOATS ((D_/2)*BQ*2 + (D_/2)*BK*2 + BK*KS_STRIDE + BQ*PS2_STRIDE*2)

// ---------- packed f32x2 helpers (SASS FFMA2 path; PTX-only) ---------------
__device__ __forceinline__ unsigned long long ffma2(unsigned long long a,
                                                    unsigned long long b,
                                                    unsigned long long c) {
    unsigned long long d;
    asm("fma.rn.f32x2 %0, %1, %2, %3;" : "=l"(d) : "l"(a), "l"(b), "l"(c));
    return d;
}
__device__ __forceinline__ unsigned long long mul2(unsigned long long a,
                                                   unsigned long long b) {
    unsigned long long d;
    asm("mul.rn.f32x2 %0, %1, %2;" : "=l"(d) : "l"(a), "l"(b));
    return d;
}
__device__ __forceinline__ unsigned long long pack2(float lo, float hi) {
    unsigned long long d;
    asm("mov.b64 %0, {%1, %2};" : "=l"(d) : "f"(lo), "f"(hi));
    return d;
}
__device__ __forceinline__ float2 unpack2(unsigned long long v) {
    float lo, hi;
    asm("mov.b64 {%0, %1}, %2;" : "=f"(lo), "=f"(hi) : "l"(v));
    return make_float2(lo, hi);
}

// Permuted position of row-element rr (0..63) inside a Qt2/Kt2 row:
// rr = 4t + 2h + r  ->  pos = h*32 + 2t + r
// so that loads of elements (4t,4t+1) and (4t+2,4t+3) are lane-contiguous.
__device__ __forceinline__ int permpos(int rr) {
    int t = rr >> 2, h = (rr >> 1) & 1, r = rr & 1;
    return h * 32 + 2 * t + r;
}

__global__ __launch_bounds__(NTHREADS, 1)
void luong_attn_kernel(const float* __restrict__ enc,
                       const float* __restrict__ dec,
                       float* __restrict__ out)
{
    extern __shared__ float sm[];
    float2* Qt2 = reinterpret_cast<float2*>(sm);               // [128][64] f2
    float2* Kt2 = Qt2 + (D_/2) * BQ;                           // [128][64] f2
    float*  Ks  = reinterpret_cast<float*>(Kt2 + (D_/2) * BK); // [64][260]
    float2* Ps2 = reinterpret_cast<float2*>(Ks + BK * KS_STRIDE); // [64][66] f2

    const int b   = blockIdx.y;
    const int t0  = blockIdx.x * BQ;
    const int tid = threadIdx.x;
    const int ty  = tid >> 4;   // q rows 4ty..4ty+3
    const int tx  = tid & 15;   // e cols 4tx..4tx+3 (GEMM1); d cols {4tx+64j} (GEMM2)

    const float* encb = enc + (size_t)b * T_ * D_;
    const float* decb = dec + (size_t)b * T_ * D_;

    // ---------------- Load Q tile -> Qt2 (transposed, d-paired, e-permuted) --
    for (int idx = tid; idx < BQ * (D_ / 4); idx += NTHREADS) {
        int r  = idx / (D_ / 4);
        int c4 = idx % (D_ / 4);
        float4 v = reinterpret_cast<const float4*>(decb + (size_t)(t0 + r) * D_)[c4];
        *reinterpret_cast<float4*>(&Ks[r * KS_STRIDE + c4 * 4]) = v;
    }
    __syncthreads();
    {
        int rr  = tid & 63;
        int pos = permpos(rr);
        for (int c4 = tid >> 6; c4 < D_ / 4; c4 += 4) {
            float4 v = *reinterpret_cast<const float4*>(&Ks[rr * KS_STRIDE + c4 * 4]);
            Qt2[(2 * c4 + 0) * BQ + pos] = make_float2(v.x, v.y);
            Qt2[(2 * c4 + 1) * BQ + pos] = make_float2(v.z, v.w);
        }
    }
    __syncthreads();

    // ---------------- Flash accumulators (packed along d) ------------------
    float m[4], l[4];
    unsigned long long acc2[4][8];   // acc2[i][2j+h]: d = 4tx + 64j + 2h .. +1
    #pragma unroll
    for (int i = 0; i < 4; i++) {
        m[i] = -CUDART_INF_F;
        l[i] = 0.0f;
        #pragma unroll
        for (int j = 0; j < 8; j++) acc2[i][j] = 0ull;
    }

    // ---------------- Main loop over encoder (key) blocks ------------------
    for (int e0 = 0; e0 < T_; e0 += BK) {
        // Load K tile: gmem (coalesced) -> Ks natural
        for (int idx = tid; idx < BK * (D_ / 4); idx += NTHREADS) {
            int r  = idx / (D_ / 4);
            int c4 = idx % (D_ / 4);
            float4 v = reinterpret_cast<const float4*>(encb + (size_t)(e0 + r) * D_)[c4];
            *reinterpret_cast<float4*>(&Ks[r * KS_STRIDE + c4 * 4]) = v;
        }
        __syncthreads();
        // Transpose Ks -> Kt2 (d-paired, e-permuted)
        {
            int rr  = tid & 63;
            int pos = permpos(rr);
            for (int c4 = tid >> 6; c4 < D_ / 4; c4 += 4) {
                float4 v = *reinterpret_cast<const float4*>(&Ks[rr * KS_STRIDE + c4 * 4]);
                Kt2[(2 * c4 + 0) * BK + pos] = make_float2(v.x, v.y);
                Kt2[(2 * c4 + 1) * BK + pos] = make_float2(v.z, v.w);
            }
        }
        __syncthreads();

        // ---- GEMM1: S2[4q][4e] += packed d-pair products -----------------
        unsigned long long S2[4][4];
        #pragma unroll
        for (int i = 0; i < 4; i++)
            #pragma unroll
            for (int j = 0; j < 4; j++) S2[i][j] = 0ull;

        {
            // lane-contiguous bases thanks to the permuted layout:
            const ulonglong2* Qa = reinterpret_cast<const ulonglong2*>(Qt2) + (ty);      // pos 2ty
            const ulonglong2* Qb = reinterpret_cast<const ulonglong2*>(Qt2) + 16 + (ty); // pos 32+2ty
            const ulonglong2* Ka = reinterpret_cast<const ulonglong2*>(Kt2) + (tx);
            const ulonglong2* Kb = reinterpret_cast<const ulonglong2*>(Kt2) + 16 + (tx);
            #pragma unroll 4
            for (int d2 = 0; d2 < D_ / 2; d2++) {
                ulonglong2 qa = Qa[d2 * 32];   // q = 4ty, 4ty+1
                ulonglong2 qb = Qb[d2 * 32];   // q = 4ty+2, 4ty+3
                ulonglong2 ka = Ka[d2 * 32];   // e = 4tx, 4tx+1
                ulonglong2 kb = Kb[d2 * 32];   // e = 4tx+2, 4tx+3
                unsigned long long q2[4] = {qa.x, qa.y, qb.x, qb.y};
                unsigned long long k2[4] = {ka.x, ka.y, kb.x, kb.y};
                #pragma unroll
                for (int i = 0; i < 4; i++)
                    #pragma unroll
                    for (int j = 0; j < 4; j++)
                        S2[i][j] = ffma2(q2[i], k2[j], S2[i][j]);
            }
        }

        // ---- Online softmax over this key block ---------------------------
        #pragma unroll
        for (int i = 0; i < 4; i++) {
            float S[4];
            #pragma unroll
            for (int j = 0; j < 4; j++) {
                float2 s = unpack2(S2[i][j]);
                S[j] = s.x + s.y;
            }
            float bm = fmaxf(fmaxf(S[0], S[1]), fmaxf(S[2], S[3]));
            #pragma unroll
            for (int off = 1; off < 16; off <<= 1)
                bm = fmaxf(bm, __shfl_xor_sync(0xffffffffu, bm, off));
            float newm  = fmaxf(m[i], bm);
            float alpha = __expf(m[i] - newm);   // 0 when m[i] == -inf

            float p0 = __expf(S[0] - newm);
            float p1 = __expf(S[1] - newm);
            float p2 = __expf(S[2] - newm);
            float p3 = __expf(S[3] - newm);
            float rs = (p0 + p1) + (p2 + p3);
            #pragma unroll
            for (int off = 1; off < 16; off <<= 1)
                rs += __shfl_xor_sync(0xffffffffu, rs, off);

            l[i] = l[i] * alpha + rs;
            m[i] = newm;
            unsigned long long aa = pack2(alpha, alpha);
            #pragma unroll
            for (int j = 0; j < 8; j++) acc2[i][j] = mul2(acc2[i][j], aa);

            // store duplicated pairs so GEMM2 reads one LDS.64 per operand
            float2* prow = &Ps2[((ty << 2) + i) * PS2_STRIDE + (tx << 2)];
            prow[0] = make_float2(p0, p0);
            prow[1] = make_float2(p1, p1);
            prow[2] = make_float2(p2, p2);
            prow[3] = make_float2(p3, p3);
        }
        __syncthreads();

        // ---- GEMM2: acc2[4q][8 d-pairs] += P[q][e] * K[e][d-pair] ---------
        const unsigned long long* Pr0 =
            reinterpret_cast<const unsigned long long*>(&Ps2[((ty << 2) + 0) * PS2_STRIDE]);
        const unsigned long long* Pr1 =
            reinterpret_cast<const unsigned long long*>(&Ps2[((ty << 2) + 1) * PS2_STRIDE]);
        const unsigned long long* Pr2 =
            reinterpret_cast<const unsigned long long*>(&Ps2[((ty << 2) + 2) * PS2_STRIDE]);
        const unsigned long long* Pr3 =
            reinterpret_cast<const unsigned long long*>(&Ps2[((ty << 2) + 3) * PS2_STRIDE]);
        #pragma unroll 2
        for (int e = 0; e < BK; e++) {
            unsigned long long pp0 = Pr0[e];
            unsigned long long pp1 = Pr1[e];
            unsigned long long pp2 = Pr2[e];
            unsigned long long pp3 = Pr3[e];
            #pragma unroll
            for (int j = 0; j < 4; j++) {
                ulonglong2 kk = *reinterpret_cast<const ulonglong2*>(
                    &Ks[e * KS_STRIDE + (tx << 2) + (j << 6)]);
                acc2[0][2*j+0] = ffma2(pp0, kk.x, acc2[0][2*j+0]);
                acc2[0][2*j+1] = ffma2(pp0, kk.y, acc2[0][2*j+1]);
                acc2[1][2*j+0] = ffma2(pp1, kk.x, acc2[1][2*j+0]);
                acc2[1][2*j+1] = ffma2(pp1, kk.y, acc2[1][2*j+1]);
                acc2[2][2*j+0] = ffma2(pp2, kk.x, acc2[2][2*j+0]);
                acc2[2][2*j+1] = ffma2(pp2, kk.y, acc2[2][2*j+1]);
                acc2[3][2*j+0] = ffma2(pp3, kk.x, acc2[3][2*j+0]);
                acc2[3][2*j+1] = ffma2(pp3, kk.y, acc2[3][2*j+1]);
            }
        }
        __syncthreads();   // before next iteration overwrites Ks/Kt2
    }

    // ---------------- Epilogue: out = [dec | acc / l] ----------------------
    #pragma unroll
    for (int i = 0; i < 4; i++) {
        float inv = 1.0f / l[i];
        size_t row = ((size_t)b * T_ + t0 + (ty << 2) + i) * (2 * D_);
        #pragma unroll
        for (int j = 0; j < 4; j++) {
            float2 a0 = unpack2(acc2[i][2*j+0]);
            float2 a1 = unpack2(acc2[i][2*j+1]);
            float4 v = make_float4(a0.x * inv, a0.y * inv, a1.x * inv, a1.y * inv);
            *reinterpret_cast<float4*>(&out[row + D_ + (tx << 2) + (j << 6)]) = v;
        }
    }
    // copy decoder rows into out[..., 0:256]
    for (int idx = tid; idx < BQ * (D_ / 4); idx += NTHREADS) {
        int r  = idx / (D_ / 4);
        int c4 = idx % (D_ / 4);
        float4 v = reinterpret_cast<const float4*>(decb + (size_t)(t0 + r) * D_)[c4];
        *reinterpret_cast<float4*>(&out[((size_t)b * T_ + t0 + r) * (2 * D_) + c4 * 4]) = v;
    }
}

extern "C" void kernel_launch(void* const* d_in, const int* in_sizes, int n_in,
                              void* d_out, int out_size)
{
    const float* enc = (const float*)d_in[0];  // encoder_outputs [8,2048,256]
    const float* dec = (const float*)d_in[1];  // decoder_outputs [8,2048,256]
    float* out = (float*)d_out;                // [8,2048,512]

    (void)in_sizes; (void)n_in; (void)out_size;

    static_assert(SMEM_FLOATS * sizeof(float) <= 232448, "smem over limit");
    cudaFuncSetAttribute(luong_attn_kernel,
                         cudaFuncAttributeMaxDynamicSharedMemorySize,
                         SMEM_FLOATS * (int)sizeof(float));

    dim3 grid(T_ / BQ, B_);
    luong_attn_kernel<<<grid, NTHREADS, SMEM_FLOATS * sizeof(float)>>>(enc, dec, out);
}

// round 4
// speedup vs baseline: 1.1691x; 1.0001x over previous
#include <cuda_runtime.h>
#include <math_constants.h>

// Problem constants (fixed by the reference: B=8, Te=Td=2048, D=256)
#define B_  8
#define T_  2048
#define D_  256
#define BQ  64
#define BK  64
#define NTHREADS 256

#define KS_STRIDE 260   // D + 4 floats padding
#define PS2_STRIDE 66   // BK + 2 (in float2 units)

// smem layout (floats):
//   Qt2 [D_/2][64] float2 (e-permuted) = 16384 floats
//   Kt2 [D_/2][64] float2 (e-permuted) = 16384 floats
//   Ks  [BK][KS_STRIDE]                = 16640 floats
//   Ps2 [BQ][PS2_STRIDE] float2        =  8448 floats
// total = 57856 floats = 231424 bytes (<= 232448 limit)
#define SMEM_FLOATS ((D_/2)*BQ*2 + (D_/2)*BK*2 + BK*KS_STRIDE + BQ*PS2_STRIDE*2)

// ---------- packed f32x2 helpers (SASS FFMA2 path; PTX-only) ---------------
__device__ __forceinline__ unsigned long long ffma2(unsigned long long a,
                                                    unsigned long long b,
                                                    unsigned long long c) {
    unsigned long long d;
    asm("fma.rn.f32x2 %0, %1, %2, %3;" : "=l"(d) : "l"(a), "l"(b), "l"(c));
    return d;
}
__device__ __forceinline__ unsigned long long mul2(unsigned long long a,
                                                   unsigned long long b) {
    unsigned long long d;
    asm("mul.rn.f32x2 %0, %1, %2;" : "=l"(d) : "l"(a), "l"(b));
    return d;
}
__device__ __forceinline__ unsigned long long pack2(float lo, float hi) {
    unsigned long long d;
    asm("mov.b64 %0, {%1, %2};" : "=l"(d) : "f"(lo), "f"(hi));
    return d;
}
__device__ __forceinline__ float2 unpack2(unsigned long long v) {
    float lo, hi;
    asm("mov.b64 {%0, %1}, %2;" : "=f"(lo), "=f"(hi) : "l"(v));
    return make_float2(lo, hi);
}

// Permuted position of row-element rr (0..63) inside a Qt2/Kt2 row:
// rr = 4t + 2h + r  ->  pos = h*32 + 2t + r
// so that loads of elements (4t,4t+1) and (4t+2,4t+3) are lane-contiguous.
__device__ __forceinline__ int permpos(int rr) {
    int t = rr >> 2, h = (rr >> 1) & 1, r = rr & 1;
    return h * 32 + 2 * t + r;
}

__global__ __launch_bounds__(NTHREADS, 1)
void luong_attn_kernel(const float* __restrict__ enc,
                       const float* __restrict__ dec,
                       float* __restrict__ out)
{
    extern __shared__ float sm[];
    float2* Qt2 = reinterpret_cast<float2*>(sm);               // [128][64] f2
    float2* Kt2 = Qt2 + (D_/2) * BQ;                           // [128][64] f2
    float*  Ks  = reinterpret_cast<float*>(Kt2 + (D_/2) * BK); // [64][260]
    float2* Ps2 = reinterpret_cast<float2*>(Ks + BK * KS_STRIDE); // [64][66] f2

    const int b   = blockIdx.y;
    const int t0  = blockIdx.x * BQ;
    const int tid = threadIdx.x;
    const int ty  = tid >> 4;   // q rows 4ty..4ty+3
    const int tx  = tid & 15;   // e cols 4tx..4tx+3 (GEMM1); d cols {4tx+64j} (GEMM2)

    const float* encb = enc + (size_t)b * T_ * D_;
    const float* decb = dec + (size_t)b * T_ * D_;

    // ---------------- Load Q tile -> Qt2 (transposed, d-paired, e-permuted) --
    for (int idx = tid; idx < BQ * (D_ / 4); idx += NTHREADS) {
        int r  = idx / (D_ / 4);
        int c4 = idx % (D_ / 4);
        float4 v = reinterpret_cast<const float4*>(decb + (size_t)(t0 + r) * D_)[c4];
        *reinterpret_cast<float4*>(&Ks[r * KS_STRIDE + c4 * 4]) = v;
    }
    __syncthreads();
    {
        int rr  = tid & 63;
        int pos = permpos(rr);
        for (int c4 = tid >> 6; c4 < D_ / 4; c4 += 4) {
            float4 v = *reinterpret_cast<const float4*>(&Ks[rr * KS_STRIDE + c4 * 4]);
            Qt2[(2 * c4 + 0) * BQ + pos] = make_float2(v.x, v.y);
            Qt2[(2 * c4 + 1) * BQ + pos] = make_float2(v.z, v.w);
        }
    }
    __syncthreads();

    // ---------------- Flash accumulators (packed along d) ------------------
    float m[4], l[4];
    unsigned long long acc2[4][8];   // acc2[i][2j+h]: d = 4tx + 64j + 2h .. +1
    #pragma unroll
    for (int i = 0; i < 4; i++) {
        m[i] = -CUDART_INF_F;
        l[i] = 0.0f;
        #pragma unroll
        for (int j = 0; j < 8; j++) acc2[i][j] = 0ull;
    }

    // ---------------- Main loop over encoder (key) blocks ------------------
    for (int e0 = 0; e0 < T_; e0 += BK) {
        // Load K tile: gmem (coalesced) -> Ks natural
        for (int idx = tid; idx < BK * (D_ / 4); idx += NTHREADS) {
            int r  = idx / (D_ / 4);
            int c4 = idx % (D_ / 4);
            float4 v = reinterpret_cast<const float4*>(encb + (size_t)(e0 + r) * D_)[c4];
            *reinterpret_cast<float4*>(&Ks[r * KS_STRIDE + c4 * 4]) = v;
        }
        __syncthreads();
        // Transpose Ks -> Kt2 (d-paired, e-permuted)
        {
            int rr  = tid & 63;
            int pos = permpos(rr);
            for (int c4 = tid >> 6; c4 < D_ / 4; c4 += 4) {
                float4 v = *reinterpret_cast<const float4*>(&Ks[rr * KS_STRIDE + c4 * 4]);
                Kt2[(2 * c4 + 0) * BK + pos] = make_float2(v.x, v.y);
                Kt2[(2 * c4 + 1) * BK + pos] = make_float2(v.z, v.w);
            }
        }
        __syncthreads();

        // ---- GEMM1: S2[4q][4e] += packed d-pair products -----------------
        unsigned long long S2[4][4];
        #pragma unroll
        for (int i = 0; i < 4; i++)
            #pragma unroll
            for (int j = 0; j < 4; j++) S2[i][j] = 0ull;

        {
            // lane-contiguous bases thanks to the permuted layout:
            const ulonglong2* Qa = reinterpret_cast<const ulonglong2*>(Qt2) + (ty);      // pos 2ty
            const ulonglong2* Qb = reinterpret_cast<const ulonglong2*>(Qt2) + 16 + (ty); // pos 32+2ty
            const ulonglong2* Ka = reinterpret_cast<const ulonglong2*>(Kt2) + (tx);
            const ulonglong2* Kb = reinterpret_cast<const ulonglong2*>(Kt2) + 16 + (tx);
            #pragma unroll 4
            for (int d2 = 0; d2 < D_ / 2; d2++) {
                ulonglong2 qa = Qa[d2 * 32];   // q = 4ty, 4ty+1
                ulonglong2 qb = Qb[d2 * 32];   // q = 4ty+2, 4ty+3
                ulonglong2 ka = Ka[d2 * 32];   // e = 4tx, 4tx+1
                ulonglong2 kb = Kb[d2 * 32];   // e = 4tx+2, 4tx+3
                unsigned long long q2[4] = {qa.x, qa.y, qb.x, qb.y};
                unsigned long long k2[4] = {ka.x, ka.y, kb.x, kb.y};
                #pragma unroll
                for (int i = 0; i < 4; i++)
                    #pragma unroll
                    for (int j = 0; j < 4; j++)
                        S2[i][j] = ffma2(q2[i], k2[j], S2[i][j]);
            }
        }

        // ---- Online softmax over this key block ---------------------------
        #pragma unroll
        for (int i = 0; i < 4; i++) {
            float S[4];
            #pragma unroll
            for (int j = 0; j < 4; j++) {
                float2 s = unpack2(S2[i][j]);
                S[j] = s.x + s.y;
            }
            float bm = fmaxf(fmaxf(S[0], S[1]), fmaxf(S[2], S[3]));
            #pragma unroll
            for (int off = 1; off < 16; off <<= 1)
                bm = fmaxf(bm, __shfl_xor_sync(0xffffffffu, bm, off));
            float newm  = fmaxf(m[i], bm);
            float alpha = __expf(m[i] - newm);   // 0 when m[i] == -inf

            float p0 = __expf(S[0] - newm);
            float p1 = __expf(S[1] - newm);
            float p2 = __expf(S[2] - newm);
            float p3 = __expf(S[3] - newm);
            float rs = (p0 + p1) + (p2 + p3);
            #pragma unroll
            for (int off = 1; off < 16; off <<= 1)
                rs += __shfl_xor_sync(0xffffffffu, rs, off);

            l[i] = l[i] * alpha + rs;
            m[i] = newm;
            unsigned long long aa = pack2(alpha, alpha);
            #pragma unroll
            for (int j = 0; j < 8; j++) acc2[i][j] = mul2(acc2[i][j], aa);

            // store duplicated pairs so GEMM2 reads one LDS.64 per operand
            float2* prow = &Ps2[((ty << 2) + i) * PS2_STRIDE + (tx << 2)];
            prow[0] = make_float2(p0, p0);
            prow[1] = make_float2(p1, p1);
            prow[2] = make_float2(p2, p2);
            prow[3] = make_float2(p3, p3);
        }
        __syncthreads();

        // ---- GEMM2: acc2[4q][8 d-pairs] += P[q][e] * K[e][d-pair] ---------
        const unsigned long long* Pr0 =
            reinterpret_cast<const unsigned long long*>(&Ps2[((ty << 2) + 0) * PS2_STRIDE]);
        const unsigned long long* Pr1 =
            reinterpret_cast<const unsigned long long*>(&Ps2[((ty << 2) + 1) * PS2_STRIDE]);
        const unsigned long long* Pr2 =
            reinterpret_cast<const unsigned long long*>(&Ps2[((ty << 2) + 2) * PS2_STRIDE]);
        const unsigned long long* Pr3 =
            reinterpret_cast<const unsigned long long*>(&Ps2[((ty << 2) + 3) * PS2_STRIDE]);
        #pragma unroll 2
        for (int e = 0; e < BK; e++) {
            unsigned long long pp0 = Pr0[e];
            unsigned long long pp1 = Pr1[e];
            unsigned long long pp2 = Pr2[e];
            unsigned long long pp3 = Pr3[e];
            #pragma unroll
            for (int j = 0; j < 4; j++) {
                ulonglong2 kk = *reinterpret_cast<const ulonglong2*>(
                    &Ks[e * KS_STRIDE + (tx << 2) + (j << 6)]);
                acc2[0][2*j+0] = ffma2(pp0, kk.x, acc2[0][2*j+0]);
                acc2[0][2*j+1] = ffma2(pp0, kk.y, acc2[0][2*j+1]);
                acc2[1][2*j+0] = ffma2(pp1, kk.x, acc2[1][2*j+0]);
                acc2[1][2*j+1] = ffma2(pp1, kk.y, acc2[1][2*j+1]);
                acc2[2][2*j+0] = ffma2(pp2, kk.x, acc2[2][2*j+0]);
                acc2[2][2*j+1] = ffma2(pp2, kk.y, acc2[2][2*j+1]);
                acc2[3][2*j+0] = ffma2(pp3, kk.x, acc2[3][2*j+0]);
                acc2[3][2*j+1] = ffma2(pp3, kk.y, acc2[3][2*j+1]);
            }
        }
        __syncthreads();   // before next iteration overwrites Ks/Kt2
    }

    // ---------------- Epilogue: out = [dec | acc / l] ----------------------
    #pragma unroll
    for (int i = 0; i < 4; i++) {
        float inv = 1.0f / l[i];
        size_t row = ((size_t)b * T_ + t0 + (ty << 2) + i) * (2 * D_);
        #pragma unroll
        for (int j = 0; j < 4; j++) {
            float2 a0 = unpack2(acc2[i][2*j+0]);
            float2 a1 = unpack2(acc2[i][2*j+1]);
            float4 v = make_float4(a0.x * inv, a0.y * inv, a1.x * inv, a1.y * inv);
            *reinterpret_cast<float4*>(&out[row + D_ + (tx << 2) + (j << 6)]) = v;
        }
    }
    // copy decoder rows into out[..., 0:256]
    for (int idx = tid; idx < BQ * (D_ / 4); idx += NTHREADS) {
        int r  = idx / (D_ / 4);
        int c4 = idx % (D_ / 4);
        float4 v = reinterpret_cast<const float4*>(decb + (size_t)(t0 + r) * D_)[c4];
        *reinterpret_cast<float4*>(&out[((size_t)b * T_ + t0 + r) * (2 * D_) + c4 * 4]) = v;
    }
}

extern "C" void kernel_launch(void* const* d_in, const int* in_sizes, int n_in,
                              void* d_out, int out_size)
{
    const float* enc = (const float*)d_in[0];  // encoder_outputs [8,2048,256]
    const float* dec = (const float*)d_in[1];  // decoder_outputs [8,2048,256]
    float* out = (float*)d_out;                // [8,2048,512]

    (void)in_sizes; (void)n_in; (void)out_size;

    static_assert(SMEM_FLOATS * sizeof(float) <= 232448, "smem over limit");
    cudaFuncSetAttribute(luong_attn_kernel,
                         cudaFuncAttributeMaxDynamicSharedMemorySize,
                         SMEM_FLOATS * (int)sizeof(float));

    dim3 grid(T_ / BQ, B_);
    luong_attn_kernel<<<grid, NTHREADS, SMEM_FLOATS * sizeof(float)>>>(enc, dec, out);
}

// round 6
// speedup vs baseline: 5.1074x; 4.3686x over previous
#include <cuda_runtime.h>
#include <cuda_fp16.h>
#include <cstdint>

#define B_  8
#define T_  2048
#define D_  256
#define BQ  128
#define BK  64
#define NIT 32          // T_/BK
#define NTH 256

// ---- f16 hi/lo images of dec (Q) and enc (K), built by pre-kernels --------
__device__ __align__(16) __half g_qhi[(size_t)B_*T_*D_];
__device__ __align__(16) __half g_qlo[(size_t)B_*T_*D_];
__device__ __align__(16) __half g_khi[(size_t)B_*T_*D_];
__device__ __align__(16) __half g_klo[(size_t)B_*T_*D_];

__device__ __forceinline__ uint32_t h2pack(__half a, __half b){
    return (uint32_t)__half_as_ushort(a) | ((uint32_t)__half_as_ushort(b) << 16);
}

__global__ void pk_q(const float* __restrict__ src){
    size_t g = (size_t)blockIdx.x * NTH + threadIdx.x;   // quads
    float4 v = ((const float4*)src)[g];
    __half hx=__float2half_rn(v.x), hy=__float2half_rn(v.y);
    __half hz=__float2half_rn(v.z), hw=__float2half_rn(v.w);
    __half lx=__float2half_rn(v.x-__half2float(hx)), ly=__float2half_rn(v.y-__half2float(hy));
    __half lz=__float2half_rn(v.z-__half2float(hz)), lw=__float2half_rn(v.w-__half2float(hw));
    ((uint2*)g_qhi)[g] = make_uint2(h2pack(hx,hy), h2pack(hz,hw));
    ((uint2*)g_qlo)[g] = make_uint2(h2pack(lx,ly), h2pack(lz,lw));
}
__global__ void pk_k(const float* __restrict__ src){
    size_t g = (size_t)blockIdx.x * NTH + threadIdx.x;
    float4 v = ((const float4*)src)[g];
    __half hx=__float2half_rn(v.x), hy=__float2half_rn(v.y);
    __half hz=__float2half_rn(v.z), hw=__float2half_rn(v.w);
    __half lx=__float2half_rn(v.x-__half2float(hx)), ly=__float2half_rn(v.y-__half2float(hy));
    __half lz=__float2half_rn(v.z-__half2float(hz)), lw=__float2half_rn(v.w-__half2float(hw));
    ((uint2*)g_khi)[g] = make_uint2(h2pack(hx,hy), h2pack(hz,hw));
    ((uint2*)g_klo)[g] = make_uint2(h2pack(lx,ly), h2pack(lz,lw));
}

// ---------------- base-ISA tensor primitives (no sm_103a features) --------
__device__ __forceinline__ void ldsm4(uint32_t r[4], uint32_t a){
    asm volatile("ldmatrix.sync.aligned.m8n8.x4.shared.b16 {%0,%1,%2,%3}, [%4];"
        : "=r"(r[0]),"=r"(r[1]),"=r"(r[2]),"=r"(r[3]) : "r"(a));
}
__device__ __forceinline__ void ldsm4t(uint32_t r[4], uint32_t a){
    asm volatile("ldmatrix.sync.aligned.m8n8.x4.trans.shared.b16 {%0,%1,%2,%3}, [%4];"
        : "=r"(r[0]),"=r"(r[1]),"=r"(r[2]),"=r"(r[3]) : "r"(a));
}
__device__ __forceinline__ void mma16816(float d[4], const uint32_t a[4], const uint32_t b[2]){
    asm volatile("mma.sync.aligned.m16n8k16.row.col.f32.f16.f16.f32 "
        "{%0,%1,%2,%3}, {%4,%5,%6,%7}, {%8,%9}, {%0,%1,%2,%3};"
        : "+f"(d[0]),"+f"(d[1]),"+f"(d[2]),"+f"(d[3])
        : "r"(a[0]),"r"(a[1]),"r"(a[2]),"r"(a[3]), "r"(b[0]),"r"(b[1]));
}

// smem: padded rows of 264 halves (528 B) -> conflict-free ldmatrix
#define ROWB   528
#define SM_QHI 0
#define SM_QLO (BQ*ROWB)            // 67584
#define SM_KHI (2*BQ*ROWB)          // 135168
#define SM_KLO (SM_KHI + BK*ROWB)   // 168960
#define SM_TOT (SM_KHI + 2*BK*ROWB) // 202752

__global__ __launch_bounds__(NTH) void attn_main(const float* __restrict__ dec,
                                                 float* __restrict__ out)
{
    extern __shared__ char smem[];
    const uint32_t smb = (uint32_t)__cvta_generic_to_shared(smem);
    const int tid = threadIdx.x, w = tid >> 5, lane = tid & 31;
    const int qt = blockIdx.x, b = blockIdx.y, t0 = qt * BQ;
    const int g = lane >> 3, lr = lane & 7;

    // ---- prologue: Q hi/lo tile -> smem (rows of 256 halves into 264-stride)
    {
        const uint4* qh = (const uint4*)(g_qhi + ((size_t)(b*T_ + t0))*D_);
        const uint4* ql = (const uint4*)(g_qlo + ((size_t)(b*T_ + t0))*D_);
        for (int i = tid; i < BQ*32; i += NTH){
            int r = i >> 5, s = i & 31;
            *(uint4*)(smem + SM_QHI + r*ROWB + s*16) = qh[r*32 + s];
            *(uint4*)(smem + SM_QLO + r*ROWB + s*16) = ql[r*32 + s];
        }
    }
    __syncthreads();

    // ---- per-thread ldmatrix base addresses
    const uint32_t aQhi = smb + SM_QHI + (uint32_t)(16*w + (g&1)*8 + lr)*ROWB + (uint32_t)(g>>1)*16;
    const uint32_t aQlo = aQhi + (SM_QLO - SM_QHI);
    const uint32_t b1Hi = smb + SM_KHI + (uint32_t)((g>>1)*8 + lr)*ROWB + (uint32_t)(g&1)*16;
    const uint32_t b1Lo = b1Hi + (SM_KLO - SM_KHI);
    const uint32_t b2Hi = smb + SM_KHI + (uint32_t)((g&1)*8 + lr)*ROWB + (uint32_t)(g>>1)*16;

    float mA = -1e30f, mB = -1e30f, lA = 0.f, lB = 0.f;
    float acc[32][4];
    #pragma unroll
    for (int j = 0; j < 32; j++){ acc[j][0]=0.f; acc[j][1]=0.f; acc[j][2]=0.f; acc[j][3]=0.f; }

    #pragma unroll 1
    for (int it = 0; it < NIT; it++){
        // ---- K hi/lo tile -> smem
        const uint4* kh = (const uint4*)(g_khi + ((size_t)(b*T_ + it*BK))*D_);
        const uint4* kl = (const uint4*)(g_klo + ((size_t)(b*T_ + it*BK))*D_);
        for (int i = tid; i < BK*32; i += NTH){
            int r = i >> 5, s = i & 31;
            *(uint4*)(smem + SM_KHI + r*ROWB + s*16) = kh[r*32 + s];
            *(uint4*)(smem + SM_KLO + r*ROWB + s*16) = kl[r*32 + s];
        }
        __syncthreads();

        // ---- GEMM1: S[16q x 64e] = Qhi*Khi + Qlo*Khi + Qhi*Klo ------------
        float S[8][4];
        #pragma unroll
        for (int j = 0; j < 8; j++){ S[j][0]=0.f; S[j][1]=0.f; S[j][2]=0.f; S[j][3]=0.f; }

        #pragma unroll
        for (int c = 0; c < 16; c++){
            uint32_t ah[4], al[4];
            ldsm4(ah, aQhi + 32u*c);
            ldsm4(al, aQlo + 32u*c);
            #pragma unroll
            for (int jj = 0; jj < 8; jj += 2){
                uint32_t bh[4], bl[4];
                ldsm4(bh, b1Hi + (uint32_t)jj*4224u + 32u*c);
                ldsm4(bl, b1Lo + (uint32_t)jj*4224u + 32u*c);
                mma16816(S[jj],   ah, bh);
                mma16816(S[jj],   al, bh);
                mma16816(S[jj],   ah, bl);
                mma16816(S[jj+1], ah, bh+2);
                mma16816(S[jj+1], al, bh+2);
                mma16816(S[jj+1], ah, bl+2);
            }
        }

        // ---- online softmax (rows rA=16w+(lane>>2), rB=rA+8) --------------
        float bmA = -1e30f, bmB = -1e30f;
        #pragma unroll
        for (int j = 0; j < 8; j++){
            bmA = fmaxf(bmA, fmaxf(S[j][0], S[j][1]));
            bmB = fmaxf(bmB, fmaxf(S[j][2], S[j][3]));
        }
        bmA = fmaxf(bmA, __shfl_xor_sync(0xffffffffu, bmA, 1));
        bmA = fmaxf(bmA, __shfl_xor_sync(0xffffffffu, bmA, 2));
        bmB = fmaxf(bmB, __shfl_xor_sync(0xffffffffu, bmB, 1));
        bmB = fmaxf(bmB, __shfl_xor_sync(0xffffffffu, bmB, 2));

        float mnA = fmaxf(mA, bmA), mnB = fmaxf(mB, bmB);
        float alphaA = __expf(mA - mnA), alphaB = __expf(mB - mnB);
        mA = mnA; mB = mnB;

        uint32_t ph[8][2];
        float sA = 0.f, sB = 0.f;
        #pragma unroll
        for (int j = 0; j < 8; j++){
            float p0 = __expf(S[j][0] - mnA), p1 = __expf(S[j][1] - mnA);
            float p2 = __expf(S[j][2] - mnB), p3 = __expf(S[j][3] - mnB);
            __half2 hA = __floats2half2_rn(p0, p1);
            __half2 hB = __floats2half2_rn(p2, p3);
            float2 fA = __half22float2(hA), fB = __half22float2(hB);
            sA += fA.x + fA.y;  sB += fB.x + fB.y;   // sum exactly what GEMM2 sees
            ph[j][0] = *(uint32_t*)&hA;
            ph[j][1] = *(uint32_t*)&hB;
        }
        sA += __shfl_xor_sync(0xffffffffu, sA, 1);
        sA += __shfl_xor_sync(0xffffffffu, sA, 2);
        sB += __shfl_xor_sync(0xffffffffu, sB, 1);
        sB += __shfl_xor_sync(0xffffffffu, sB, 2);
        lA = lA * alphaA + sA;
        lB = lB * alphaB + sB;

        if (!__all_sync(0xffffffffu, (alphaA == 1.f) & (alphaB == 1.f))){
            #pragma unroll
            for (int j = 0; j < 32; j++){
                acc[j][0] *= alphaA; acc[j][1] *= alphaA;
                acc[j][2] *= alphaB; acc[j][3] *= alphaB;
            }
        }

        // ---- GEMM2: acc[16q x 256d] += P[16q x 64e] * K[64e x 256d] -------
        #pragma unroll
        for (int kc = 0; kc < 4; kc++){
            uint32_t a[4] = { ph[2*kc][0], ph[2*kc][1], ph[2*kc+1][0], ph[2*kc+1][1] };
            #pragma unroll
            for (int jj = 0; jj < 32; jj += 2){
                uint32_t bb[4];
                ldsm4t(bb, b2Hi + (uint32_t)kc*8448u + (uint32_t)jj*16u);
                mma16816(acc[jj],   a, bb);
                mma16816(acc[jj+1], a, bb+2);
            }
        }
        __syncthreads();   // before next iter overwrites K tiles
    }

    // ---- epilogue: out[.., 256:512] = acc / l ; out[.., 0:256] = dec ------
    {
        int rA = 16*w + (lane >> 2);
        float ivA = 1.f / lA, ivB = 1.f / lB;
        float* oA = out + ((size_t)(b*T_ + t0 + rA))    *(size_t)(2*D_) + D_ + (lane&3)*2;
        float* oB = out + ((size_t)(b*T_ + t0 + rA + 8))*(size_t)(2*D_) + D_ + (lane&3)*2;
        #pragma unroll
        for (int j = 0; j < 32; j++){
            *(float2*)(oA + 8*j) = make_float2(acc[j][0]*ivA, acc[j][1]*ivA);
            *(float2*)(oB + 8*j) = make_float2(acc[j][2]*ivB, acc[j][3]*ivB);
        }
    }
    for (int i = tid; i < BQ*(D_/4); i += NTH){
        int r = i >> 6, c4 = i & 63;
        float4 v = *(const float4*)(dec + ((size_t)(b*T_ + t0 + r))*D_ + 4*c4);
        *(float4*)(out + ((size_t)(b*T_ + t0 + r))*(size_t)(2*D_) + 4*c4) = v;
    }
}

extern "C" void kernel_launch(void* const* d_in, const int* in_sizes, int n_in,
                              void* d_out, int out_size)
{
    const float* enc = (const float*)d_in[0];  // encoder_outputs [8,2048,256]
    const float* dec = (const float*)d_in[1];  // decoder_outputs [8,2048,256]
    float* out = (float*)d_out;                // [8,2048,512]
    (void)in_sizes; (void)n_in; (void)out_size;

    const int quads = B_*T_*D_/4;              // 1,048,576
    pk_q<<<quads/NTH, NTH>>>(dec);
    pk_k<<<quads/NTH, NTH>>>(enc);

    cudaFuncSetAttribute(attn_main, cudaFuncAttributeMaxDynamicSharedMemorySize, SM_TOT);
    dim3 grid(T_/BQ, B_);                      // (16, 8) = 128 CTAs, single wave
    attn_main<<<grid, NTH, SM_TOT>>>(dec, out);
}